// round 4
// baseline (speedup 1.0000x reference)
#include <cuda_runtime.h>
#include <cuda_bf16.h>

// ---------------------------------------------------------------------------
// LorentzLayer: out[b,a] = sum_{c,d} G[c][d][a] * T[b,c,d]
// G_c = Bi_mat @ (W_c * B_c) computed in closed form by a tiny kernel.
// Main kernel: HBM-bound streaming GEMV (262144 x 400) @ (400 x 4).
// Round 3: push occupancy 3 -> 4 blocks/SM (regs 80 -> <=64 via unroll 3).
// ---------------------------------------------------------------------------

#define NCLUSTER 100
#define BATCH_N  262144
#define GPAD     20            // floats per cluster in smem (16 data + 4 pad)

__device__ float g_combined[NCLUSTER * 16];   // layout [c][d][a], a contiguous

__device__ __forceinline__ void build_boost(float B[4][4],
                                            float b0, float b1, float b2) {
    float mag2 = b0 * b0 + b1 * b1 + b2 * b2;
    float g = 1.0f / sqrtf(1.0f - mag2);
    float inv_mag2 = 1.0f / mag2;
    float gm1 = g - 1.0f;

    B[0][0] = g;
    B[0][1] = -g * b0; B[0][2] = -g * b1; B[0][3] = -g * b2;
    B[1][0] = -g * b0; B[2][0] = -g * b1; B[3][0] = -g * b2;

    float bb[3] = {b0, b1, b2};
    #pragma unroll
    for (int i = 0; i < 3; i++) {
        #pragma unroll
        for (int j = 0; j < 3; j++) {
            float v = gm1 * bb[i] * bb[j] * inv_mag2;
            if (i == j) v += 1.0f;
            B[i + 1][j + 1] = v;
        }
    }
}

__global__ void precompute_kernel(const float* __restrict__ Bo,
                                  const float* __restrict__ Bi,
                                  const float* __restrict__ W) {
    int c = threadIdx.x;
    if (c >= NCLUSTER) return;

    float Bim[4][4];
    build_boost(Bim, Bi[0], Bi[1], Bi[2]);

    float Bc[4][4];
    build_boost(Bc, Bo[c * 3 + 0], Bo[c * 3 + 1], Bo[c * 3 + 2]);

    float w = W[c];

    #pragma unroll
    for (int a = 0; a < 4; a++) {
        #pragma unroll
        for (int d = 0; d < 4; d++) {
            float s = 0.0f;
            #pragma unroll
            for (int m = 0; m < 4; m++)
                s += Bim[a][m] * Bc[m][d];
            g_combined[c * 16 + d * 4 + a] = s * w;   // [c][d][a]
        }
    }
}

// 8 warps/block, each warp covers 16 rows (2 rows per thread).
// lane = (rloc << 2) | cluster_phase.
#define ROWS_PER_BLOCK 128     // 8 warps * 16 rows

__global__ __launch_bounds__(256, 4)
void lorentz_main_kernel(const float* __restrict__ T, float* __restrict__ out) {
    __shared__ float gs[NCLUSTER * GPAD];

    int tid = threadIdx.x;
    for (int i = tid; i < NCLUSTER * 16; i += 256) {
        int c = i >> 4;
        int r = i & 15;
        gs[c * GPAD + r] = g_combined[i];
    }
    __syncthreads();

    int warp = tid >> 5;
    int lane = tid & 31;
    int sub  = lane & 3;        // cluster phase 0..3
    int rloc = lane >> 2;       // 0..7

    int row0 = (blockIdx.x * 8 + warp) * 16 + rloc;
    int row1 = row0 + 8;
    const float4* tin0 = (const float4*)(T + (size_t)row0 * 400);
    const float4* tin1 = (const float4*)(T + (size_t)row1 * 400);

    float ax0 = 0.f, ay0 = 0.f, az0 = 0.f, aw0 = 0.f;
    float ax1 = 0.f, ay1 = 0.f, az1 = 0.f, aw1 = 0.f;

    #pragma unroll 3
    for (int i = 0; i < 25; i++) {
        int c = i * 4 + sub;
        float4 v0 = __ldcs(&tin0[c]);
        float4 v1 = __ldcs(&tin1[c]);
        const float4* gp = (const float4*)(&gs[c * GPAD]);
        float4 g0 = gp[0];
        float4 g1 = gp[1];
        float4 g2 = gp[2];
        float4 g3 = gp[3];
        ax0 += v0.x * g0.x + v0.y * g1.x + v0.z * g2.x + v0.w * g3.x;
        ay0 += v0.x * g0.y + v0.y * g1.y + v0.z * g2.y + v0.w * g3.y;
        az0 += v0.x * g0.z + v0.y * g1.z + v0.z * g2.z + v0.w * g3.z;
        aw0 += v0.x * g0.w + v0.y * g1.w + v0.z * g2.w + v0.w * g3.w;
        ax1 += v1.x * g0.x + v1.y * g1.x + v1.z * g2.x + v1.w * g3.x;
        ay1 += v1.x * g0.y + v1.y * g1.y + v1.z * g2.y + v1.w * g3.y;
        az1 += v1.x * g0.z + v1.y * g1.z + v1.z * g2.z + v1.w * g3.z;
        aw1 += v1.x * g0.w + v1.y * g1.w + v1.z * g2.w + v1.w * g3.w;
    }

    // reduce across the 4 cluster-phase lanes (xor 1, then xor 2)
    const unsigned FULL = 0xffffffffu;
    ax0 += __shfl_xor_sync(FULL, ax0, 1);
    ay0 += __shfl_xor_sync(FULL, ay0, 1);
    az0 += __shfl_xor_sync(FULL, az0, 1);
    aw0 += __shfl_xor_sync(FULL, aw0, 1);
    ax1 += __shfl_xor_sync(FULL, ax1, 1);
    ay1 += __shfl_xor_sync(FULL, ay1, 1);
    az1 += __shfl_xor_sync(FULL, az1, 1);
    aw1 += __shfl_xor_sync(FULL, aw1, 1);
    ax0 += __shfl_xor_sync(FULL, ax0, 2);
    ay0 += __shfl_xor_sync(FULL, ay0, 2);
    az0 += __shfl_xor_sync(FULL, az0, 2);
    aw0 += __shfl_xor_sync(FULL, aw0, 2);
    ax1 += __shfl_xor_sync(FULL, ax1, 2);
    ay1 += __shfl_xor_sync(FULL, ay1, 2);
    az1 += __shfl_xor_sync(FULL, az1, 2);
    aw1 += __shfl_xor_sync(FULL, aw1, 2);

    if (sub == 0) {
        ((float4*)out)[row0] = make_float4(ax0, ay0, az0, aw0);
        ((float4*)out)[row1] = make_float4(ax1, ay1, az1, aw1);
    }
}

extern "C" void kernel_launch(void* const* d_in, const int* in_sizes, int n_in,
                              void* d_out, int out_size) {
    const float* T  = (const float*)d_in[0];   // (262144, 100, 4)
    const float* Bo = (const float*)d_in[1];   // (100, 3)
    const float* Bi = (const float*)d_in[2];   // (1, 3)
    const float* W  = (const float*)d_in[3];   // (100, 1)
    // d_in[4] = K_mats — encoded analytically in build_boost.

    float* out = (float*)d_out;                // (262144, 1, 4)

    precompute_kernel<<<1, 128>>>(Bo, Bi, W);

    int grid = BATCH_N / ROWS_PER_BLOCK;       // 262144 / 128 = 2048
    lorentz_main_kernel<<<grid, 256>>>(T, out);
}

// round 7
// speedup vs baseline: 1.0616x; 1.0616x over previous
#include <cuda_runtime.h>
#include <cuda_bf16.h>

// ---------------------------------------------------------------------------
// LorentzLayer: out[b,a] = sum_{c,d} G[c][d][a] * T[b,c,d]
// G_c = Bi_mat @ (W_c * B_c) computed in closed form by a tiny kernel.
// Main kernel: HBM-bound streaming GEMV (262144 x 400) @ (400 x 4).
// Round 6: persistent kernel (grid=444, one resident wave) with STATIC
// interleaved warp work assignment (no atomics — hedge against repeated
// container failures on the atomic-ticket variant). Prologue amortized,
// tail ceiling 86.5% -> 92.3%.
// ---------------------------------------------------------------------------

#define NCLUSTER 100
#define BATCH_N  262144
#define GPAD     20            // floats per cluster in smem (16 data + 4 pad)

#define NBLOCKS  444           // 148 SMs * 3 resident blocks
#define NWARPS   (NBLOCKS * 8) // 3552 persistent warps
#define UNIT_ROWS 16
#define NUNITS   (BATCH_N / UNIT_ROWS)   // 16384

__device__ float g_combined[NCLUSTER * 16];   // layout [c][d][a], a contiguous

__device__ __forceinline__ void build_boost(float B[4][4],
                                            float b0, float b1, float b2) {
    float mag2 = b0 * b0 + b1 * b1 + b2 * b2;
    float g = 1.0f / sqrtf(1.0f - mag2);
    float inv_mag2 = 1.0f / mag2;
    float gm1 = g - 1.0f;

    B[0][0] = g;
    B[0][1] = -g * b0; B[0][2] = -g * b1; B[0][3] = -g * b2;
    B[1][0] = -g * b0; B[2][0] = -g * b1; B[3][0] = -g * b2;

    float bb[3] = {b0, b1, b2};
    #pragma unroll
    for (int i = 0; i < 3; i++) {
        #pragma unroll
        for (int j = 0; j < 3; j++) {
            float v = gm1 * bb[i] * bb[j] * inv_mag2;
            if (i == j) v += 1.0f;
            B[i + 1][j + 1] = v;
        }
    }
}

__global__ void precompute_kernel(const float* __restrict__ Bo,
                                  const float* __restrict__ Bi,
                                  const float* __restrict__ W) {
    int c = threadIdx.x;
    if (c >= NCLUSTER) return;

    float Bim[4][4];
    build_boost(Bim, Bi[0], Bi[1], Bi[2]);

    float Bc[4][4];
    build_boost(Bc, Bo[c * 3 + 0], Bo[c * 3 + 1], Bo[c * 3 + 2]);

    float w = W[c];

    #pragma unroll
    for (int a = 0; a < 4; a++) {
        #pragma unroll
        for (int d = 0; d < 4; d++) {
            float s = 0.0f;
            #pragma unroll
            for (int m = 0; m < 4; m++)
                s += Bim[a][m] * Bc[m][d];
            g_combined[c * 16 + d * 4 + a] = s * w;   // [c][d][a]
        }
    }
}

// 8 warps/block. Each warp processes 16-row units (2 rows per thread),
// striding by the total warp count. lane = (rloc << 2) | cluster_phase.
__global__ __launch_bounds__(256, 3)
void lorentz_main_kernel(const float* __restrict__ T, float* __restrict__ out) {
    __shared__ float gs[NCLUSTER * GPAD];

    int tid = threadIdx.x;
    for (int i = tid; i < NCLUSTER * 16; i += 256) {
        int c = i >> 4;
        int r = i & 15;
        gs[c * GPAD + r] = g_combined[i];
    }
    __syncthreads();

    int warp = tid >> 5;
    int lane = tid & 31;
    int sub  = lane & 3;        // cluster phase 0..3
    int rloc = lane >> 2;       // 0..7
    const unsigned FULL = 0xffffffffu;

    int wid = blockIdx.x * 8 + warp;

    for (int cur = wid; cur < NUNITS; cur += NWARPS) {
        int row0 = cur * UNIT_ROWS + rloc;
        int row1 = row0 + 8;
        const float4* tin0 = (const float4*)(T + (size_t)row0 * 400);
        const float4* tin1 = (const float4*)(T + (size_t)row1 * 400);

        float ax0 = 0.f, ay0 = 0.f, az0 = 0.f, aw0 = 0.f;
        float ax1 = 0.f, ay1 = 0.f, az1 = 0.f, aw1 = 0.f;

        #pragma unroll 5
        for (int i = 0; i < 25; i++) {
            int c = i * 4 + sub;
            float4 v0 = __ldcs(&tin0[c]);
            float4 v1 = __ldcs(&tin1[c]);
            const float4* gp = (const float4*)(&gs[c * GPAD]);
            float4 g0 = gp[0];
            float4 g1 = gp[1];
            float4 g2 = gp[2];
            float4 g3 = gp[3];
            ax0 += v0.x * g0.x + v0.y * g1.x + v0.z * g2.x + v0.w * g3.x;
            ay0 += v0.x * g0.y + v0.y * g1.y + v0.z * g2.y + v0.w * g3.y;
            az0 += v0.x * g0.z + v0.y * g1.z + v0.z * g2.z + v0.w * g3.z;
            aw0 += v0.x * g0.w + v0.y * g1.w + v0.z * g2.w + v0.w * g3.w;
            ax1 += v1.x * g0.x + v1.y * g1.x + v1.z * g2.x + v1.w * g3.x;
            ay1 += v1.x * g0.y + v1.y * g1.y + v1.z * g2.y + v1.w * g3.y;
            az1 += v1.x * g0.z + v1.y * g1.z + v1.z * g2.z + v1.w * g3.z;
            aw1 += v1.x * g0.w + v1.y * g1.w + v1.z * g2.w + v1.w * g3.w;
        }

        // reduce across the 4 cluster-phase lanes (xor 1, then xor 2)
        ax0 += __shfl_xor_sync(FULL, ax0, 1);
        ay0 += __shfl_xor_sync(FULL, ay0, 1);
        az0 += __shfl_xor_sync(FULL, az0, 1);
        aw0 += __shfl_xor_sync(FULL, aw0, 1);
        ax1 += __shfl_xor_sync(FULL, ax1, 1);
        ay1 += __shfl_xor_sync(FULL, ay1, 1);
        az1 += __shfl_xor_sync(FULL, az1, 1);
        aw1 += __shfl_xor_sync(FULL, aw1, 1);
        ax0 += __shfl_xor_sync(FULL, ax0, 2);
        ay0 += __shfl_xor_sync(FULL, ay0, 2);
        az0 += __shfl_xor_sync(FULL, az0, 2);
        aw0 += __shfl_xor_sync(FULL, aw0, 2);
        ax1 += __shfl_xor_sync(FULL, ax1, 2);
        ay1 += __shfl_xor_sync(FULL, ay1, 2);
        az1 += __shfl_xor_sync(FULL, az1, 2);
        aw1 += __shfl_xor_sync(FULL, aw1, 2);

        if (sub == 0) {
            ((float4*)out)[row0] = make_float4(ax0, ay0, az0, aw0);
            ((float4*)out)[row1] = make_float4(ax1, ay1, az1, aw1);
        }
    }
}

extern "C" void kernel_launch(void* const* d_in, const int* in_sizes, int n_in,
                              void* d_out, int out_size) {
    const float* T  = (const float*)d_in[0];   // (262144, 100, 4)
    const float* Bo = (const float*)d_in[1];   // (100, 3)
    const float* Bi = (const float*)d_in[2];   // (1, 3)
    const float* W  = (const float*)d_in[3];   // (100, 1)
    // d_in[4] = K_mats — encoded analytically in build_boost.

    float* out = (float*)d_out;                // (262144, 1, 4)

    precompute_kernel<<<1, 128>>>(Bo, Bi, W);

    lorentz_main_kernel<<<NBLOCKS, 256>>>(T, out);
}